// round 7
// baseline (speedup 1.0000x reference)
#include <cuda_runtime.h>
#include <cstdint>
#include <math.h>

// ---------------------------------------------------------------------------
// cross_entropy_with_hnm_for_one_class_detection (GB300)
//
// Branch b: (B=32, 2/4/6/6 channel planes of HxW), b0: 320x320, b1: 160x160.
//   p1 = softmax(score)[:,1];  pos = l0>0.5;  neg = l1>0.5
//   neg_prob = has_pos ? (neg ? p1 : 0) : p1
//   k = has_pos ? min(5*pos_num, neg_num) : N/10
//   thr = k-th smallest of neg_prob          (exact, via radix select on bits)
//   loss_score = [ sum_pos -l0*log p0 + sum_{neg_prob<=thr} -l1*log p1 ] / cnt
//   loss_bbox  = sum(((bbox - l[2:6])*mask[2:6])^2) / max(sum mask,1e-8)  (0 if sum==0)
// Output: [loss_total, ls0, lb0, ls1, lb1]
//
// p1 (and neg flag in its sign bit) is cached in scratch; exact k-th smallest
// via 12/10/10-bit radix select (all candidates are non-negative floats, so
// uint order == float order). When the rank falls inside the forced-zero
// block (common), threshold is exactly 0 and all radix passes early-exit.
// ---------------------------------------------------------------------------

#define BATCH 32
static const int MAXN0 = 32 * 320 * 320;   // 3,276,800
static const int MAXN1 = 32 * 160 * 160;   //   819,200
static const int MAXNT = MAXN0 + MAXN1;    // 4,096,000

struct BState {
    unsigned long long pos_num;
    unsigned long long neg_num;
    unsigned long long sel_cnt;
    double pos_ce;
    double neg_ce;
    double sq;
    double msum;
    unsigned prefix;     // radix prefix so far
    unsigned rem;        // remaining rank within current bucket set
    unsigned thr_bits;   // final threshold bit pattern
    int has_pos;
    int need;            // 1 if radix select required (thr != 0 case)
    int needfb;          // 1 if fallback hist over non-neg needed (!has_pos)
    int pad;
};

__device__ BState   g_state[2];
__device__ unsigned g_pu[MAXNT];          // bits(p1) | (neg << 31)
__device__ unsigned g_hist1[2][4096];     // level-1 histogram over candidates
__device__ unsigned g_hist2[2][1024];     // levels 2/3 (reused)

// ---------------------------------------------------------------------------
__global__ void k_init() {
    int t = blockIdx.x * blockDim.x + threadIdx.x;
    int stride = gridDim.x * blockDim.x;
    unsigned* a = &g_hist1[0][0];
    for (int i = t; i < 2 * 4096; i += stride) a[i] = 0;
    unsigned* c = &g_hist2[0][0];
    for (int i = t; i < 2 * 1024; i += stride) c[i] = 0;
    unsigned* s = (unsigned*)g_state;
    int nw = (int)(sizeof(g_state) / 4);
    for (int i = t; i < nw; i += stride) s[i] = 0;
}

// ---------------------------------------------------------------------------
// Pass 1: all threshold-independent reductions + p1/neg scratch + neg-only
// level-1 histogram (hidden under the DRAM-bound mainloop).
// Blocks [0,G0) -> branch 0, [G0,grid) -> branch 1. 4 pixels per thread/iter.
// ---------------------------------------------------------------------------
__global__ void k_pass1(const float* __restrict__ sc0, const float* __restrict__ bb0,
                        const float* __restrict__ gm0, const float* __restrict__ gl0,
                        const float* __restrict__ sc1, const float* __restrict__ bb1,
                        const float* __restrict__ gm1, const float* __restrict__ gl1,
                        int HW0, int HW1, int N0, int N1, int G0)
{
    __shared__ unsigned sh[4096];
    for (int i = threadIdx.x; i < 4096; i += blockDim.x) sh[i] = 0;
    __syncthreads();

    int br, lb, Gb, HW, Nb, gofs;
    const float *sc, *bb, *gm, *gl;
    if (blockIdx.x < G0) { br = 0; lb = blockIdx.x;      Gb = G0;             HW = HW0; Nb = N0; gofs = 0;  sc = sc0; bb = bb0; gm = gm0; gl = gl0; }
    else                 { br = 1; lb = blockIdx.x - G0; Gb = gridDim.x - G0; HW = HW1; Nb = N1; gofs = N0; sc = sc1; bb = bb1; gm = gm1; gl = gl1; }

    unsigned cpos = 0, cneg = 0;
    float a_posce = 0.f, a_sq = 0.f, a_m = 0.f;

    int nq = Nb >> 2;
    int stride = Gb * blockDim.x;
    for (int q = lb * blockDim.x + threadIdx.x; q < nq; q += stride) {
        int i = q << 2;
        int n = i / HW;
        int s = i - n * HW;
        size_t b2 = (size_t)n * 2 * HW + s;
        size_t b4 = (size_t)n * 4 * HW + s;
        size_t b6 = (size_t)n * 6 * HW + s;

        float4 V0 = *reinterpret_cast<const float4*>(sc + b2);
        float4 V1 = *reinterpret_cast<const float4*>(sc + b2 + HW);
        float4 L0 = *reinterpret_cast<const float4*>(gl + b6);
        float4 L1 = *reinterpret_cast<const float4*>(gl + b6 + HW);

        float v0a[4] = {V0.x, V0.y, V0.z, V0.w};
        float v1a[4] = {V1.x, V1.y, V1.z, V1.w};
        float l0a[4] = {L0.x, L0.y, L0.z, L0.w};
        float l1a[4] = {L1.x, L1.y, L1.z, L1.w};
        unsigned outw[4];

        #pragma unroll
        for (int j = 0; j < 4; j++) {
            float d = v1a[j] - v0a[j];
            float e = expf(d);
            float denom = 1.0f + e;
            float p1 = __fdividef(e, denom);
            bool pos = l0a[j] > 0.5f;
            bool neg = l1a[j] > 0.5f;
            cpos += pos ? 1u : 0u;
            cneg += neg ? 1u : 0u;
            if (pos) a_posce += l0a[j] * logf(denom);   // -l0*log p0 = l0*log(1+e)
            unsigned ub = __float_as_uint(p1);
            if (neg) atomicAdd(&sh[ub >> 20], 1u);
            outw[j] = ub | (neg ? 0x80000000u : 0u);
        }
        *reinterpret_cast<uint4*>(&g_pu[gofs + i]) =
            make_uint4(outw[0], outw[1], outw[2], outw[3]);

        // bbox branch (threshold-independent)
        #pragma unroll
        for (int c = 0; c < 4; c++) {
            float4 MK = *reinterpret_cast<const float4*>(gm + b6 + (size_t)(2 + c) * HW);
            float4 TG = *reinterpret_cast<const float4*>(gl + b6 + (size_t)(2 + c) * HW);
            float4 PV = *reinterpret_cast<const float4*>(bb + b4 + (size_t)c * HW);
            float mk[4] = {MK.x, MK.y, MK.z, MK.w};
            float tg[4] = {TG.x, TG.y, TG.z, TG.w};
            float pv[4] = {PV.x, PV.y, PV.z, PV.w};
            #pragma unroll
            for (int j = 0; j < 4; j++) {
                float dd = (pv[j] - tg[j]) * mk[j];
                a_sq += dd * dd;
                a_m  += mk[j];
            }
        }
    }
    __syncthreads();

    for (int i = threadIdx.x; i < 4096; i += blockDim.x)
        if (sh[i]) atomicAdd(&g_hist1[br][i], sh[i]);

    // warp-reduce (to double), one atomic per warp
    unsigned long long rp = cpos, rn = cneg;
    double dce = (double)a_posce, dsq = (double)a_sq, dm = (double)a_m;
    for (int o = 16; o > 0; o >>= 1) {
        rp  += __shfl_down_sync(0xffffffffu, rp, o);
        rn  += __shfl_down_sync(0xffffffffu, rn, o);
        dce += __shfl_down_sync(0xffffffffu, dce, o);
        dsq += __shfl_down_sync(0xffffffffu, dsq, o);
        dm  += __shfl_down_sync(0xffffffffu, dm, o);
    }
    if ((threadIdx.x & 31) == 0) {
        atomicAdd(&g_state[br].pos_num, rp);
        atomicAdd(&g_state[br].neg_num, rn);
        atomicAdd(&g_state[br].pos_ce, dce);
        atomicAdd(&g_state[br].sq, dsq);
        atomicAdd(&g_state[br].msum, dm);
    }
}

// ---------------------------------------------------------------------------
// Prep: compute k, rank r; decide whether radix select is needed at all.
// Candidates = (has_pos ? neg elements : all elements); the (N-neg) forced
// zeros occupy the lowest ranks when has_pos.
// ---------------------------------------------------------------------------
__global__ void k_prep(int N0, int N1)
{
    int br = threadIdx.x;
    if (br >= 2) return;
    BState& st = g_state[br];
    unsigned long long N = (unsigned long long)(br ? N1 : N0);
    unsigned long long pos = st.pos_num, neg = st.neg_num;
    int hp = (pos > 0) ? 1 : 0;
    st.has_pos = hp;
    unsigned long long k;
    if (hp) { unsigned long long kp = 5ull * pos; k = (kp < neg) ? kp : neg; }
    else    { k = N / 10ull; }
    long long idx = (long long)k - 1;            // jnp.take default mode = clip
    if (idx < 0) idx = 0;
    if (idx > (long long)N - 1) idx = (long long)N - 1;
    unsigned long long r = (unsigned long long)idx + 1;   // 1-indexed rank
    unsigned long long zeros = hp ? (N - neg) : 0ull;
    if (r <= zeros) {
        st.need = 0;                              // threshold is exactly 0.0
        st.thr_bits = 0;
    } else {
        st.need = 1;
        st.rem = (unsigned)(r - zeros);           // rank within candidates
        st.needfb = hp ? 0 : 1;                   // !has_pos: hist missing non-negs
    }
}

// ---------------------------------------------------------------------------
// Fallback (only when !has_pos): add non-neg elements into the level-1 hist.
// ---------------------------------------------------------------------------
__global__ void k_histFB(int N0, int N1, int G0)
{
    int br, lb, Gb, Nb, gofs;
    if (blockIdx.x < G0) { br = 0; lb = blockIdx.x;      Gb = G0;             Nb = N0; gofs = 0;  }
    else                 { br = 1; lb = blockIdx.x - G0; Gb = gridDim.x - G0; Nb = N1; gofs = N0; }
    if (!g_state[br].needfb) return;

    __shared__ unsigned sh[4096];
    for (int i = threadIdx.x; i < 4096; i += blockDim.x) sh[i] = 0;
    __syncthreads();

    int nq = Nb >> 2;
    int stride = Gb * blockDim.x;
    for (int q = lb * blockDim.x + threadIdx.x; q < nq; q += stride) {
        uint4 w = *reinterpret_cast<const uint4*>(&g_pu[gofs + (q << 2)]);
        unsigned a[4] = {w.x, w.y, w.z, w.w};
        #pragma unroll
        for (int j = 0; j < 4; j++)
            if (!(a[j] >> 31)) atomicAdd(&sh[(a[j] & 0x7fffffffu) >> 20], 1u);
    }
    __syncthreads();
    for (int i = threadIdx.x; i < 4096; i += blockDim.x)
        if (sh[i]) atomicAdd(&g_hist1[br][i], sh[i]);
}

// ---------------------------------------------------------------------------
// Level-1 scan over 4096 bins. blockDim = 256, one block per branch.
// ---------------------------------------------------------------------------
__global__ void k_scan1()
{
    int br = blockIdx.x;
    BState& st = g_state[br];
    if (!st.need) return;
    __shared__ unsigned sh[4096];
    __shared__ unsigned partial[256];
    unsigned long long r = (unsigned long long)st.rem;

    for (int i = threadIdx.x; i < 4096; i += 256) sh[i] = g_hist1[br][i];
    __syncthreads();

    unsigned ps = 0;
    #pragma unroll
    for (int j = 0; j < 16; j++) ps += sh[threadIdx.x * 16 + j];
    partial[threadIdx.x] = ps;
    __syncthreads();

    if (threadIdx.x == 0) {
        unsigned long long cum = 0;
        int seg = 0;
        while (seg < 255 && cum + partial[seg] < r) { cum += partial[seg]; seg++; }
        int bin = seg * 16;
        while (bin < seg * 16 + 15 && cum + sh[bin] < r) { cum += sh[bin]; bin++; }
        st.prefix = (unsigned)bin;
        st.rem    = (unsigned)(r - cum);
    }
}

// ---------------------------------------------------------------------------
// Levels 2 & 3 histogram over candidates within current prefix.
// ---------------------------------------------------------------------------
__global__ void k_histL(int level, int N0, int N1, int G0)
{
    int br, lb, Gb, Nb, gofs;
    if (blockIdx.x < G0) { br = 0; lb = blockIdx.x;      Gb = G0;             Nb = N0; gofs = 0;  }
    else                 { br = 1; lb = blockIdx.x - G0; Gb = gridDim.x - G0; Nb = N1; gofs = N0; }
    BState& st = g_state[br];
    if (!st.need) return;

    __shared__ unsigned sh[1024];
    for (int i = threadIdx.x; i < 1024; i += blockDim.x) sh[i] = 0;
    __syncthreads();

    int hp = st.has_pos;
    unsigned prefix = st.prefix;
    int nq = Nb >> 2;
    int stride = Gb * blockDim.x;
    for (int q = lb * blockDim.x + threadIdx.x; q < nq; q += stride) {
        uint4 w = *reinterpret_cast<const uint4*>(&g_pu[gofs + (q << 2)]);
        unsigned a[4] = {w.x, w.y, w.z, w.w};
        #pragma unroll
        for (int j = 0; j < 4; j++) {
            bool cand = hp ? (a[j] >> 31) : true;
            unsigned eb = a[j] & 0x7fffffffu;
            bool match = (level == 2) ? ((eb >> 20) == prefix) : ((eb >> 10) == prefix);
            if (cand && match) {
                unsigned bin = (level == 2) ? ((eb >> 10) & 1023u) : (eb & 1023u);
                atomicAdd(&sh[bin], 1u);
            }
        }
    }
    __syncthreads();
    for (int i = threadIdx.x; i < 1024; i += blockDim.x)
        if (sh[i]) atomicAdd(&g_hist2[br][i], sh[i]);
}

// Levels 2 & 3 scan over 1024 bins. blockDim = 256, one block per branch.
__global__ void k_scanL(int level)
{
    int br = blockIdx.x;
    BState& st = g_state[br];
    if (!st.need) return;
    __shared__ unsigned sh[1024];
    __shared__ unsigned partial[256];
    unsigned long long r = (unsigned long long)st.rem;

    for (int i = threadIdx.x; i < 1024; i += 256) sh[i] = g_hist2[br][i];
    __syncthreads();
    if (level == 2)
        for (int i = threadIdx.x; i < 1024; i += 256) g_hist2[br][i] = 0;

    unsigned ps = 0;
    #pragma unroll
    for (int j = 0; j < 4; j++) ps += sh[threadIdx.x * 4 + j];
    partial[threadIdx.x] = ps;
    __syncthreads();

    if (threadIdx.x == 0) {
        unsigned long long cum = 0;
        int seg = 0;
        while (seg < 255 && cum + partial[seg] < r) { cum += partial[seg]; seg++; }
        int bin = seg * 4;
        while (bin < seg * 4 + 3 && cum + sh[bin] < r) { cum += sh[bin]; bin++; }
        if (level == 2) { st.prefix = (st.prefix << 10) | (unsigned)bin; st.rem = (unsigned)(r - cum); }
        else            { st.thr_bits = (st.prefix << 10) | (unsigned)bin; }
    }
}

// ---------------------------------------------------------------------------
// Final pass: count + sum -l1*log(p1) over elements with neg_prob <= thr.
// (When has_pos, non-neg elements have neg_prob == 0 and are always selected.)
// ---------------------------------------------------------------------------
__global__ void k_final(const float* __restrict__ gl0, const float* __restrict__ gl1,
                        int HW0, int HW1, int N0, int N1, int G0)
{
    int br, lb, Gb, Nb, gofs, HW;
    const float* gl;
    if (blockIdx.x < G0) { br = 0; lb = blockIdx.x;      Gb = G0;             Nb = N0; gofs = 0;  HW = HW0; gl = gl0; }
    else                 { br = 1; lb = blockIdx.x - G0; Gb = gridDim.x - G0; Nb = N1; gofs = N0; HW = HW1; gl = gl1; }

    BState& st = g_state[br];
    int hp = st.has_pos;
    unsigned thr = st.thr_bits;   // uint compare == float compare (non-neg floats)

    unsigned cnt = 0;
    float acc = 0.f;
    int nq = Nb >> 2;
    int stride = Gb * blockDim.x;
    for (int q = lb * blockDim.x + threadIdx.x; q < nq; q += stride) {
        int i = q << 2;
        int n = i / HW;
        int s = i - n * HW;
        uint4 w = *reinterpret_cast<const uint4*>(&g_pu[gofs + i]);
        float4 L1 = *reinterpret_cast<const float4*>(gl + ((size_t)n * 6 + 1) * HW + s);
        unsigned a[4] = {w.x, w.y, w.z, w.w};
        float l1a[4] = {L1.x, L1.y, L1.z, L1.w};
        #pragma unroll
        for (int j = 0; j < 4; j++) {
            unsigned eb = a[j] & 0x7fffffffu;
            unsigned cmpv = (hp && !(a[j] >> 31)) ? 0u : eb;
            if (cmpv <= thr) {
                acc -= l1a[j] * logf(__uint_as_float(eb));
                cnt++;
            }
        }
    }

    unsigned long long rc = cnt;
    double da = (double)acc;
    for (int o = 16; o > 0; o >>= 1) {
        rc += __shfl_down_sync(0xffffffffu, rc, o);
        da += __shfl_down_sync(0xffffffffu, da, o);
    }
    if ((threadIdx.x & 31) == 0) {
        atomicAdd(&st.sel_cnt, rc);
        atomicAdd(&st.neg_ce, da);
    }
}

// ---------------------------------------------------------------------------
__global__ void k_fin(float* out, int out_size)
{
    double tot = 0.0;
    double vals[4];
    for (int br = 0; br < 2; br++) {
        BState& st = g_state[br];
        unsigned long long cnt = st.pos_num + st.sel_cnt;
        if (cnt < 1) cnt = 1;
        double ls = (st.pos_ce + st.neg_ce) / (double)cnt;
        double denom = (st.msum > 1e-8) ? st.msum : 1e-8;
        double lb = (st.msum > 0.0) ? (st.sq / denom) : 0.0;
        vals[2 * br]     = ls;
        vals[2 * br + 1] = lb;
        tot += ls + lb;
    }
    if (out_size >= 1) out[0] = (float)tot;
    for (int j = 0; j < 4 && j + 1 < out_size; j++) out[j + 1] = (float)vals[j];
    for (int j = 5; j < out_size; j++) out[j] = 0.0f;
}

// ---------------------------------------------------------------------------
extern "C" void kernel_launch(void* const* d_in, const int* in_sizes, int n_in,
                              void* d_out, int out_size)
{
    const float* sc0 = (const float*)d_in[0];
    const float* bb0 = (const float*)d_in[1];
    const float* gm0 = (const float*)d_in[2];
    const float* gl0 = (const float*)d_in[3];
    const float* sc1 = (const float*)d_in[4];
    const float* bb1 = (const float*)d_in[5];
    const float* gm1 = (const float*)d_in[6];
    const float* gl1 = (const float*)d_in[7];

    int HW0 = in_sizes[0] / (BATCH * 2);
    int HW1 = in_sizes[4] / (BATCH * 2);
    int N0 = BATCH * HW0;
    int N1 = BATCH * HW1;

    // grid split proportional to N0:N1 = 4:1
    const int G0 = 592, G1 = 148, G = G0 + G1;
    const int T = 256;

    k_init  <<<32, T>>>();
    k_pass1 <<<G, T>>>(sc0, bb0, gm0, gl0, sc1, bb1, gm1, gl1, HW0, HW1, N0, N1, G0);
    k_prep  <<<1, 32>>>(N0, N1);
    k_histFB<<<G, T>>>(N0, N1, G0);
    k_scan1 <<<2, 256>>>();
    k_histL <<<G, T>>>(2, N0, N1, G0);
    k_scanL <<<2, 256>>>(2);
    k_histL <<<G, T>>>(3, N0, N1, G0);
    k_scanL <<<2, 256>>>(3);
    k_final <<<G, T>>>(gl0, gl1, HW0, HW1, N0, N1, G0);
    k_fin   <<<1, 1>>>((float*)d_out, out_size);
}